// round 14
// baseline (speedup 1.0000x reference)
#include <cuda_runtime.h>
#include <cuda_fp16.h>
#include <math.h>
#include <stdint.h>

#define T 2048      // tokens
#define DM 2048     // model dim
#define FF 2048     // ffn dim
#define NE 8        // experts
#define BM 64
#define BN 128
#define BK 32
#define NKT (DM/BK)   // 64 k-stages per GEMM

// smem layout (all fp16)
#define A_STRIDE_H 40                      // halfs per A row (32+8 pad): ldsm conflict-free
#define B_STRIDE_H 136                     // halfs per B row (128+8 pad): ldsm.trans conflict-free
#define A_BYTES (BM * A_STRIDE_H * 2)      // 5120
#define B_BYTES_H (BK * B_STRIDE_H * 2)    // 8704
#define GU_STAGE (A_BYTES + 2 * B_BYTES_H) // 22528
#define GU_SMEM  (2 * GU_STAGE)            // 45056
#define DN_STAGE (A_BYTES + B_BYTES_H)     // 13824
#define DN_SMEM  (2 * DN_STAGE)            // 27648

// ---------------- scratch (device globals) ----------------
__device__ __align__(16) __half g_xs[(size_t)T * DM];   // fp16(x * score)
__device__ __align__(16) __half g_xr[(size_t)T * DM];   // fp16(x)
__device__ __align__(16) __half g_h [(size_t)T * FF];   // fp16(routed swiglu), permuted rows
__device__ __align__(16) __half g_hs[(size_t)T * FF];   // fp16(shared swiglu), token rows
__device__ int g_eidx[T];
__device__ int g_counts[NE];
__device__ int g_offsets[NE];
__device__ int g_cursor[NE];
__device__ int g_perm[T];

// ---------------- PTX helpers ----------------
__device__ __forceinline__ void cp16(uint32_t dst, const void* src, bool pred) {
    int bytes = pred ? 16 : 0;
    asm volatile("cp.async.cg.shared.global [%0], [%1], 16, %2;"
                 :: "r"(dst), "l"(src), "r"(bytes) : "memory");
}
#define CP_COMMIT() asm volatile("cp.async.commit_group;" ::: "memory")
#define CP_WAIT0()  asm volatile("cp.async.wait_group 0;" ::: "memory")

__device__ __forceinline__ uint32_t smem_u32(const void* p) {
    uint32_t a;
    asm("{ .reg .u64 t; cvta.to.shared.u64 t, %1; cvt.u32.u64 %0, t; }" : "=r"(a) : "l"(p));
    return a;
}
__device__ __forceinline__ uint32_t h2(float hi, float lo) {
    uint32_t d;
    asm("cvt.rn.f16x2.f32 %0, %1, %2;" : "=r"(d) : "f"(hi), "f"(lo));
    return d;
}
__device__ __forceinline__ void mma16(float* c, const uint32_t* a, uint32_t b0, uint32_t b1) {
    asm volatile("mma.sync.aligned.m16n8k16.row.col.f32.f16.f16.f32 "
                 "{%0,%1,%2,%3}, {%4,%5,%6,%7}, {%8,%9}, {%0,%1,%2,%3};"
                 : "+f"(c[0]), "+f"(c[1]), "+f"(c[2]), "+f"(c[3])
                 : "r"(a[0]), "r"(a[1]), "r"(a[2]), "r"(a[3]), "r"(b0), "r"(b1));
}
__device__ __forceinline__ void ldsm4(uint32_t* r, uint32_t addr) {
    asm volatile("ldmatrix.sync.aligned.m8n8.x4.shared.b16 {%0,%1,%2,%3}, [%4];"
                 : "=r"(r[0]), "=r"(r[1]), "=r"(r[2]), "=r"(r[3]) : "r"(addr));
}
__device__ __forceinline__ void ldsm4t(uint32_t* r, uint32_t addr) {
    asm volatile("ldmatrix.sync.aligned.m8n8.x4.trans.shared.b16 {%0,%1,%2,%3}, [%4];"
                 : "=r"(r[0]), "=r"(r[1]), "=r"(r[2]), "=r"(r[3]) : "r"(addr));
}
__device__ __forceinline__ uint4 pack8(float4 v0, float4 v1) {
    uint4 o;
    o.x = h2(v0.y, v0.x); o.y = h2(v0.w, v0.z);
    o.z = h2(v1.y, v1.x); o.w = h2(v1.w, v1.z);
    return o;
}

// ---------------- router / routing bookkeeping ----------------
__global__ void init_kernel() { if (threadIdx.x < NE) g_counts[threadIdx.x] = 0; }

__global__ void __launch_bounds__(256) router_kernel(const float* __restrict__ x,
                                                     const float* __restrict__ rw) {
    int t = blockIdx.x;
    const float* xr = x + (size_t)t * DM;
    float acc[NE];
#pragma unroll
    for (int e = 0; e < NE; e++) acc[e] = 0.f;
    for (int d = threadIdx.x; d < DM; d += 256) {
        float xv = xr[d];
        const float* r = rw + (size_t)d * NE;
#pragma unroll
        for (int e = 0; e < NE; e++) acc[e] = fmaf(xv, r[e], acc[e]);
    }
    __shared__ float sacc[8][NE];
    __shared__ float s_score;
    int lane = threadIdx.x & 31, warp = threadIdx.x >> 5;
#pragma unroll
    for (int e = 0; e < NE; e++) {
        float v = acc[e];
#pragma unroll
        for (int o = 16; o > 0; o >>= 1) v += __shfl_down_sync(0xffffffffu, v, o);
        if (lane == 0) sacc[warp][e] = v;
    }
    __syncthreads();
    if (threadIdx.x == 0) {
        float best = -INFINITY; int bi = 0;
#pragma unroll
        for (int e = 0; e < NE; e++) {
            float v = 0.f;
#pragma unroll
            for (int w = 0; w < 8; w++) v += sacc[w][e];
            if (v > best) { best = v; bi = e; }
        }
        s_score = 1.f / (1.f + expf(-best));
        g_eidx[t] = bi;
        atomicAdd(&g_counts[bi], 1);
    }
    __syncthreads();
    float sc = s_score;
    for (int d = threadIdx.x; d < DM; d += 256) {
        float xv = xr[d];
        g_xs[(size_t)t * DM + d] = __float2half_rn(xv * sc);
        g_xr[(size_t)t * DM + d] = __float2half_rn(xv);
    }
}

__global__ void scan_kernel() {
    if (threadIdx.x == 0) {
        int off = 0;
        for (int e = 0; e < NE; e++) { g_offsets[e] = off; g_cursor[e] = off; off += g_counts[e]; }
    }
}
__global__ void scatter_kernel() {
    int t = blockIdx.x * blockDim.x + threadIdx.x;
    if (t < T) { int e = g_eidx[t]; int pos = atomicAdd(&g_cursor[e], 1); g_perm[pos] = t; }
}

// ================= gate/up GEMM + fused SwiGLU (merged routed z<8 / shared z==8) =================
// 256 threads, 8 warps 2x4, warp tile 32x32 (mt=2, nt=4), BM=64
__global__ void __launch_bounds__(256) gateup_mma(const float* __restrict__ Wg_all,
                                                  const float* __restrict__ Wu_all,
                                                  const float* __restrict__ Wsg,
                                                  const float* __restrict__ Wsu) {
    int e = blockIdx.z;
    bool sh = (e == NE);
    int Mcnt = sh ? T : g_counts[e];
    int base = sh ? 0 : g_offsets[e];
    int m0 = blockIdx.y * BM;
    if (m0 >= Mcnt) return;
    int n0 = blockIdx.x * BN;
    const __half* A = sh ? g_xr : g_xs;
    __half* Hout = sh ? g_hs : g_h;
    const float* Wg = sh ? Wsg : Wg_all + (size_t)e * DM * FF;
    const float* Wu = sh ? Wsu : Wu_all + (size_t)e * DM * FF;

    extern __shared__ char smem[];
    uint32_t sb = smem_u32(smem);
    int tid = threadIdx.x, wid = tid >> 5, lane = tid & 31;
    int wm = wid >> 2, wn = wid & 3;          // 2x4 grid, warp tile 32x32
    int grp = lane >> 2, tg = lane & 3;

    uint32_t a_lm = (uint32_t)((((lane & 15) + wm * 32) * A_STRIDE_H + (lane >> 4) * 8) * 2);
    uint32_t b_lm = (uint32_t)(((((lane & 7) + ((lane >> 3) & 1) * 8) * B_STRIDE_H)
                               + wn * 32 + (lane >> 4) * 8) * 2);

    // ---- A copy: row tid/4 (0..63), 8-half chunk (tid&3) ----
    const __half* arow = nullptr;
    uint32_t asoA;
    int q0 = (tid & 3) * 8;
    {
        int r = tid >> 2;
        int gr = m0 + r;
        if (gr < Mcnt) {
            int tok = sh ? gr : g_perm[base + gr];
            arow = A + (size_t)tok * DM;
        }
        asoA = (uint32_t)((r * A_STRIDE_H + q0) * 2);
    }
    // ---- B load/convert: n8 = tid&15 (8-float chunk), kb = tid>>4 -> rows kb, kb+16 ----
    int n8 = tid & 15, kb = tid >> 4;
    const float* bgp = Wg + (size_t)kb * FF + n0 + n8 * 8;
    const float* bup = Wu + (size_t)kb * FF + n0 + n8 * 8;
    uint32_t bsts[2];
#pragma unroll
    for (int i = 0; i < 2; i++)
        bsts[i] = (uint32_t)(((kb + i * 16) * B_STRIDE_H + n8 * 8) * 2);

    float accg[2][4][4], accu[2][4][4];
#pragma unroll
    for (int mt = 0; mt < 2; mt++)
#pragma unroll
        for (int nt = 0; nt < 4; nt++)
#pragma unroll
            for (int c = 0; c < 4; c++) { accg[mt][nt][c] = 0.f; accu[mt][nt][c] = 0.f; }

    float4 vg[4], vu[4];

    auto ldgB = [&](int kt) {
        size_t k0 = (size_t)kt * BK * FF;
#pragma unroll
        for (int i = 0; i < 2; i++) {
            const float* g = bgp + k0 + (size_t)i * 16 * FF;
            const float* u = bup + k0 + (size_t)i * 16 * FF;
            vg[i * 2 + 0] = *(const float4*)(g);
            vg[i * 2 + 1] = *(const float4*)(g + 4);
            vu[i * 2 + 0] = *(const float4*)(u);
            vu[i * 2 + 1] = *(const float4*)(u + 4);
        }
    };
    auto ldA = [&](int kt, int b) {
        uint32_t sA = sb + b * GU_STAGE;
        int k0 = kt * BK;
        cp16(sA + asoA, arow ? (const void*)(arow + k0 + q0) : (const void*)g_xs, arow != nullptr);
    };
    auto stsB = [&](int b) {
#pragma unroll
        for (int i = 0; i < 2; i++) {
            *(uint4*)((char*)smem + (b * GU_STAGE + A_BYTES) + bsts[i]) = pack8(vg[i * 2], vg[i * 2 + 1]);
            *(uint4*)((char*)smem + (b * GU_STAGE + A_BYTES + B_BYTES_H) + bsts[i]) = pack8(vu[i * 2], vu[i * 2 + 1]);
        }
    };

    ldgB(0);
    ldA(0, 0); CP_COMMIT();
    stsB(0);
    CP_WAIT0();
    __syncthreads();

    for (int kt = 0; kt < NKT; kt++) {
        int b = kt & 1;
        bool pre = (kt + 1 < NKT);
        if (pre) {
            ldgB(kt + 1);
            ldA(kt + 1, b ^ 1); CP_COMMIT();
        }
        uint32_t sA = sb + b * GU_STAGE;
        uint32_t sG = sA + A_BYTES;
        uint32_t sU = sG + B_BYTES_H;
        uint32_t abase = sA + a_lm;
        uint32_t gbase = sG + b_lm;
        uint32_t ubase = sU + b_lm;
#pragma unroll
        for (int kk = 0; kk < 2; kk++) {
            int kr = kk * 16;
            uint32_t af[2][4];
#pragma unroll
            for (int mt = 0; mt < 2; mt++)
                ldsm4(af[mt], abase + (uint32_t)((mt * 16 * A_STRIDE_H + kr) * 2));
            uint32_t bg[2][4], bu[2][4];
#pragma unroll
            for (int p = 0; p < 2; p++) {
                ldsm4t(bg[p], gbase + (uint32_t)((kr * B_STRIDE_H + p * 16) * 2));
                ldsm4t(bu[p], ubase + (uint32_t)((kr * B_STRIDE_H + p * 16) * 2));
            }
#pragma unroll
            for (int p = 0; p < 2; p++)
#pragma unroll
                for (int mt = 0; mt < 2; mt++) {
                    mma16(accg[mt][2 * p + 0], af[mt], bg[p][0], bg[p][1]);
                    mma16(accg[mt][2 * p + 1], af[mt], bg[p][2], bg[p][3]);
                    mma16(accu[mt][2 * p + 0], af[mt], bu[p][0], bu[p][1]);
                    mma16(accu[mt][2 * p + 1], af[mt], bu[p][2], bu[p][3]);
                }
        }
        if (pre) {
            stsB(b ^ 1);
            CP_WAIT0();
        }
        __syncthreads();
    }

    // ---- epilogue: h = fp16(silu(g) * u) ----
#pragma unroll
    for (int mt = 0; mt < 2; mt++) {
        int row0 = m0 + wm * 32 + mt * 16 + grp;
#pragma unroll
        for (int half = 0; half < 2; half++) {
            int r = row0 + half * 8;
            if (r < Mcnt) {
                __half* orow = Hout + (size_t)(base + r) * FF + n0 + wn * 32;
#pragma unroll
                for (int nt = 0; nt < 4; nt++) {
                    float gx = accg[mt][nt][half * 2 + 0];
                    float gy = accg[mt][nt][half * 2 + 1];
                    float hx = gx / (1.f + expf(-gx)) * accu[mt][nt][half * 2 + 0];
                    float hy = gy / (1.f + expf(-gy)) * accu[mt][nt][half * 2 + 1];
                    *(__half2*)(orow + nt * 8 + tg * 2) = __floats2half2_rn(hx, hy);
                }
            }
        }
    }
}

// ================= fused down GEMM: out = h·Wd[e] + hs·Wsd, single write =================
// 256 threads, warp tile 32x32 (mt=2), BM=64, 128 k-stages (two K=2048 passes)
__global__ void __launch_bounds__(256, 2) down_mma(const float* __restrict__ W_all,
                                                   const float* __restrict__ Wsd,
                                                   float* __restrict__ Out) {
    int e    = blockIdx.z;
    int Mcnt = g_counts[e];
    int base = g_offsets[e];
    int m0 = blockIdx.y * BM;
    if (m0 >= Mcnt) return;
    int n0 = blockIdx.x * BN;
    const float* W1 = W_all + (size_t)e * FF * DM;

    extern __shared__ char smem[];
    uint32_t sb = smem_u32(smem);
    int tid = threadIdx.x, wid = tid >> 5, lane = tid & 31;
    int wm = wid >> 2, wn = wid & 3;
    int grp = lane >> 2, tg = lane & 3;

    uint32_t a_lm = (uint32_t)((((lane & 15) + wm * 32) * A_STRIDE_H + (lane >> 4) * 8) * 2);
    uint32_t b_lm = (uint32_t)(((((lane & 7) + ((lane >> 3) & 1) * 8) * B_STRIDE_H)
                               + wn * 32 + (lane >> 4) * 8) * 2);

    // ---- A copy: row tid/4, chunk tid&3; two sources (phase 0: g_h permuted, phase 1: g_hs[tok])
    const __half* arow1 = nullptr;
    const __half* arow2 = nullptr;
    uint32_t asoA;
    int q0 = (tid & 3) * 8;
    {
        int r = tid >> 2;
        int gr = m0 + r;
        if (gr < Mcnt) {
            arow1 = g_h + (size_t)(base + gr) * FF;
            arow2 = g_hs + (size_t)g_perm[base + gr] * FF;
        }
        asoA = (uint32_t)((r * A_STRIDE_H + q0) * 2);
    }
    int n8 = tid & 15, kb = tid >> 4;
    const float* wp1 = W1  + (size_t)kb * DM + n0 + n8 * 8;
    const float* wp2 = Wsd + (size_t)kb * DM + n0 + n8 * 8;
    uint32_t bsts[2];
#pragma unroll
    for (int i = 0; i < 2; i++)
        bsts[i] = (uint32_t)(((kb + i * 16) * B_STRIDE_H + n8 * 8) * 2);

    float acc[2][4][4];
#pragma unroll
    for (int mt = 0; mt < 2; mt++)
#pragma unroll
        for (int nt = 0; nt < 4; nt++)
#pragma unroll
            for (int c = 0; c < 4; c++) acc[mt][nt][c] = 0.f;

    float4 vw[4];

    auto ldgB = [&](int kt) {
        const float* wp = (kt >= NKT) ? wp2 : wp1;
        size_t k0 = (size_t)(kt & (NKT - 1)) * BK * DM;
#pragma unroll
        for (int i = 0; i < 2; i++) {
            const float* w = wp + k0 + (size_t)i * 16 * DM;
            vw[i * 2 + 0] = *(const float4*)(w);
            vw[i * 2 + 1] = *(const float4*)(w + 4);
        }
    };
    auto ldA = [&](int kt, int b) {
        const __half* ar = (kt >= NKT) ? arow2 : arow1;
        uint32_t sA = sb + b * DN_STAGE;
        int k0 = (kt & (NKT - 1)) * BK;
        cp16(sA + asoA, ar ? (const void*)(ar + k0 + q0) : (const void*)g_h, ar != nullptr);
    };
    auto stsB = [&](int b) {
#pragma unroll
        for (int i = 0; i < 2; i++)
            *(uint4*)((char*)smem + (b * DN_STAGE + A_BYTES) + bsts[i]) = pack8(vw[i * 2], vw[i * 2 + 1]);
    };

    ldgB(0);
    ldA(0, 0); CP_COMMIT();
    stsB(0);
    CP_WAIT0();
    __syncthreads();

    const int NKT2 = 2 * NKT;
    for (int kt = 0; kt < NKT2; kt++) {
        int b = kt & 1;
        bool pre = (kt + 1 < NKT2);
        if (pre) {
            ldgB(kt + 1);
            ldA(kt + 1, b ^ 1); CP_COMMIT();
        }
        uint32_t sA = sb + b * DN_STAGE;
        uint32_t sB = sA + A_BYTES;
        uint32_t abase = sA + a_lm;
        uint32_t bbase = sB + b_lm;
#pragma unroll
        for (int kk = 0; kk < 2; kk++) {
            int kr = kk * 16;
            uint32_t af[2][4];
#pragma unroll
            for (int mt = 0; mt < 2; mt++)
                ldsm4(af[mt], abase + (uint32_t)((mt * 16 * A_STRIDE_H + kr) * 2));
            uint32_t bf[2][4];
#pragma unroll
            for (int p = 0; p < 2; p++)
                ldsm4t(bf[p], bbase + (uint32_t)((kr * B_STRIDE_H + p * 16) * 2));
#pragma unroll
            for (int p = 0; p < 2; p++)
#pragma unroll
                for (int mt = 0; mt < 2; mt++) {
                    mma16(acc[mt][2 * p + 0], af[mt], bf[p][0], bf[p][1]);
                    mma16(acc[mt][2 * p + 1], af[mt], bf[p][2], bf[p][3]);
                }
        }
        if (pre) {
            stsB(b ^ 1);
            CP_WAIT0();
        }
        __syncthreads();
    }

    // ---- epilogue: single write, scatter to token rows ----
#pragma unroll
    for (int mt = 0; mt < 2; mt++) {
        int row0 = m0 + wm * 32 + mt * 16 + grp;
#pragma unroll
        for (int half = 0; half < 2; half++) {
            int r = row0 + half * 8;
            if (r < Mcnt) {
                int tok = g_perm[base + r];
                float* orow = Out + (size_t)tok * DM + n0 + wn * 32;
#pragma unroll
                for (int nt = 0; nt < 4; nt++) {
                    float vx = acc[mt][nt][half * 2 + 0];
                    float vy = acc[mt][nt][half * 2 + 1];
                    *(float2*)(orow + nt * 8 + tg * 2) = make_float2(vx, vy);
                }
            }
        }
    }
}

// ---------------- launch ----------------
extern "C" void kernel_launch(void* const* d_in, const int* in_sizes, int n_in,
                              void* d_out, int out_size) {
    const float* hidden   = (const float*)d_in[0];
    const float* router_w = (const float*)d_in[1];
    const float* gate_w   = (const float*)d_in[2];
    const float* up_w     = (const float*)d_in[3];
    const float* down_w   = (const float*)d_in[4];
    const float* sgate    = (const float*)d_in[5];
    const float* sup      = (const float*)d_in[6];
    const float* sdown    = (const float*)d_in[7];
    float* out = (float*)d_out;

    cudaFuncSetAttribute(gateup_mma, cudaFuncAttributeMaxDynamicSharedMemorySize, GU_SMEM);
    cudaFuncSetAttribute(down_mma,   cudaFuncAttributeMaxDynamicSharedMemorySize, DN_SMEM);

    init_kernel<<<1, 32>>>();
    router_kernel<<<T, 256>>>(hidden, router_w);
    scan_kernel<<<1, 32>>>();
    scatter_kernel<<<T / 256, 256>>>();

    dim3 gg(FF / BN, T / BM, NE + 1);   // 16 x 32 x 9; z 0..7 routed, 8 = shared
    gateup_mma<<<gg, 256, GU_SMEM>>>(gate_w, up_w, sgate, sup);

    dim3 dd(DM / BN, T / BM, NE);       // 16 x 32 x 8; fused routed+shared down
    down_mma<<<dd, 256, DN_SMEM>>>(down_w, sdown, out);
}

// round 16
// speedup vs baseline: 1.0087x; 1.0087x over previous
#include <cuda_runtime.h>
#include <cuda_fp16.h>
#include <math.h>
#include <stdint.h>

#define T 2048      // tokens
#define DM 2048     // model dim
#define FF 2048     // ffn dim
#define NE 8        // experts
#define BM 128
#define BN 128
#define BK 32
#define NKT (DM/BK)   // 64 k-stages per K=2048 GEMM

// smem layout (all fp16)
#define A_STRIDE_H 40                      // halfs per A row (32+8 pad): ldsm conflict-free
#define B_STRIDE_H 136                     // halfs per B row (128+8 pad): ldsm.trans conflict-free
#define A_BYTES (BM * A_STRIDE_H * 2)      // 10240
#define B_BYTES_H (BK * B_STRIDE_H * 2)    // 8704
#define GU_STAGE (A_BYTES + 2 * B_BYTES_H) // 27648
#define GU_SMEM  (2 * GU_STAGE)            // 55296
#define DN_STAGE (A_BYTES + B_BYTES_H)     // 18944
#define DN_SMEM  (2 * DN_STAGE)            // 37888

// ---------------- scratch (device globals) ----------------
__device__ __align__(16) __half g_xs[(size_t)T * DM];   // fp16(x * score)
__device__ __align__(16) __half g_xr[(size_t)T * DM];   // fp16(x)
__device__ __align__(16) __half g_h [(size_t)T * FF];   // fp16(routed swiglu), permuted rows
__device__ __align__(16) __half g_hs[(size_t)T * FF];   // fp16(shared swiglu), token rows
__device__ int g_eidx[T];
__device__ int g_counts[NE];
__device__ int g_offsets[NE];
__device__ int g_cursor[NE];
__device__ int g_perm[T];

// ---------------- PTX helpers ----------------
__device__ __forceinline__ void cp16(uint32_t dst, const void* src, bool pred) {
    int bytes = pred ? 16 : 0;
    asm volatile("cp.async.cg.shared.global [%0], [%1], 16, %2;"
                 :: "r"(dst), "l"(src), "r"(bytes) : "memory");
}
#define CP_COMMIT() asm volatile("cp.async.commit_group;" ::: "memory")
#define CP_WAIT0()  asm volatile("cp.async.wait_group 0;" ::: "memory")

__device__ __forceinline__ uint32_t smem_u32(const void* p) {
    uint32_t a;
    asm("{ .reg .u64 t; cvta.to.shared.u64 t, %1; cvt.u32.u64 %0, t; }" : "=r"(a) : "l"(p));
    return a;
}
__device__ __forceinline__ uint32_t h2(float hi, float lo) {
    uint32_t d;
    asm("cvt.rn.f16x2.f32 %0, %1, %2;" : "=r"(d) : "f"(hi), "f"(lo));
    return d;
}
__device__ __forceinline__ void mma16(float* c, const uint32_t* a, uint32_t b0, uint32_t b1) {
    asm volatile("mma.sync.aligned.m16n8k16.row.col.f32.f16.f16.f32 "
                 "{%0,%1,%2,%3}, {%4,%5,%6,%7}, {%8,%9}, {%0,%1,%2,%3};"
                 : "+f"(c[0]), "+f"(c[1]), "+f"(c[2]), "+f"(c[3])
                 : "r"(a[0]), "r"(a[1]), "r"(a[2]), "r"(a[3]), "r"(b0), "r"(b1));
}
__device__ __forceinline__ void ldsm4(uint32_t* r, uint32_t addr) {
    asm volatile("ldmatrix.sync.aligned.m8n8.x4.shared.b16 {%0,%1,%2,%3}, [%4];"
                 : "=r"(r[0]), "=r"(r[1]), "=r"(r[2]), "=r"(r[3]) : "r"(addr));
}
__device__ __forceinline__ void ldsm4t(uint32_t* r, uint32_t addr) {
    asm volatile("ldmatrix.sync.aligned.m8n8.x4.trans.shared.b16 {%0,%1,%2,%3}, [%4];"
                 : "=r"(r[0]), "=r"(r[1]), "=r"(r[2]), "=r"(r[3]) : "r"(addr));
}
__device__ __forceinline__ uint4 pack8(float4 v0, float4 v1) {
    uint4 o;
    o.x = h2(v0.y, v0.x); o.y = h2(v0.w, v0.z);
    o.z = h2(v1.y, v1.x); o.w = h2(v1.w, v1.z);
    return o;
}

// ---------------- router / routing bookkeeping ----------------
__global__ void init_kernel() { if (threadIdx.x < NE) g_counts[threadIdx.x] = 0; }

__global__ void __launch_bounds__(256) router_kernel(const float* __restrict__ x,
                                                     const float* __restrict__ rw) {
    int t = blockIdx.x;
    const float* xr = x + (size_t)t * DM;
    float acc[NE];
#pragma unroll
    for (int e = 0; e < NE; e++) acc[e] = 0.f;
    for (int d = threadIdx.x; d < DM; d += 256) {
        float xv = xr[d];
        const float* r = rw + (size_t)d * NE;
#pragma unroll
        for (int e = 0; e < NE; e++) acc[e] = fmaf(xv, r[e], acc[e]);
    }
    __shared__ float sacc[8][NE];
    __shared__ float s_score;
    int lane = threadIdx.x & 31, warp = threadIdx.x >> 5;
#pragma unroll
    for (int e = 0; e < NE; e++) {
        float v = acc[e];
#pragma unroll
        for (int o = 16; o > 0; o >>= 1) v += __shfl_down_sync(0xffffffffu, v, o);
        if (lane == 0) sacc[warp][e] = v;
    }
    __syncthreads();
    if (threadIdx.x == 0) {
        float best = -INFINITY; int bi = 0;
#pragma unroll
        for (int e = 0; e < NE; e++) {
            float v = 0.f;
#pragma unroll
            for (int w = 0; w < 8; w++) v += sacc[w][e];
            if (v > best) { best = v; bi = e; }
        }
        s_score = 1.f / (1.f + expf(-best));
        g_eidx[t] = bi;
        atomicAdd(&g_counts[bi], 1);
    }
    __syncthreads();
    float sc = s_score;
    for (int d = threadIdx.x; d < DM; d += 256) {
        float xv = xr[d];
        g_xs[(size_t)t * DM + d] = __float2half_rn(xv * sc);
        g_xr[(size_t)t * DM + d] = __float2half_rn(xv);
    }
}

__global__ void scan_kernel() {
    if (threadIdx.x == 0) {
        int off = 0;
        for (int e = 0; e < NE; e++) { g_offsets[e] = off; g_cursor[e] = off; off += g_counts[e]; }
    }
}
__global__ void scatter_kernel() {
    int t = blockIdx.x * blockDim.x + threadIdx.x;
    if (t < T) { int e = g_eidx[t]; int pos = atomicAdd(&g_cursor[e], 1); g_perm[pos] = t; }
}

// ================= gate/up GEMM + fused SwiGLU (merged routed z<8 / shared z==8) =================
// 256 threads, 8 warps 2x4, warp tile 64x32 (mt=4, nt=4), BM=128
__global__ void __launch_bounds__(256) gateup_mma(const float* __restrict__ Wg_all,
                                                  const float* __restrict__ Wu_all,
                                                  const float* __restrict__ Wsg,
                                                  const float* __restrict__ Wsu) {
    int e = blockIdx.z;
    bool sh = (e == NE);
    int Mcnt = sh ? T : g_counts[e];
    int base = sh ? 0 : g_offsets[e];
    int m0 = blockIdx.y * BM;
    if (m0 >= Mcnt) return;
    int n0 = blockIdx.x * BN;
    const __half* A = sh ? g_xr : g_xs;
    __half* Hout = sh ? g_hs : g_h;
    const float* Wg = sh ? Wsg : Wg_all + (size_t)e * DM * FF;
    const float* Wu = sh ? Wsu : Wu_all + (size_t)e * DM * FF;

    extern __shared__ char smem[];
    uint32_t sb = smem_u32(smem);
    int tid = threadIdx.x, wid = tid >> 5, lane = tid & 31;
    int wm = wid >> 2, wn = wid & 3;
    int grp = lane >> 2, tg = lane & 3;

    uint32_t a_lm = (uint32_t)((((lane & 15) + wm * 64) * A_STRIDE_H + (lane >> 4) * 8) * 2);
    uint32_t b_lm = (uint32_t)(((((lane & 7) + ((lane >> 3) & 1) * 8) * B_STRIDE_H)
                               + wn * 32 + (lane >> 4) * 8) * 2);

    // ---- A copy: row tid/2, 16-half chunk (tid&1) ----
    const __half* arow = nullptr;
    uint32_t asoA;
    int q0 = (tid & 1) * 16;
    {
        int r = tid >> 1;
        int gr = m0 + r;
        if (gr < Mcnt) {
            int tok = sh ? gr : g_perm[base + gr];
            arow = A + (size_t)tok * DM;
        }
        asoA = (uint32_t)((r * A_STRIDE_H + q0) * 2);
    }
    // ---- B load/convert: n8 = tid&15 (8-float chunk), kb = tid>>4 -> rows kb, kb+16 ----
    int n8 = tid & 15, kb = tid >> 4;
    const float* bgp = Wg + (size_t)kb * FF + n0 + n8 * 8;
    const float* bup = Wu + (size_t)kb * FF + n0 + n8 * 8;
    uint32_t bsts[2];
#pragma unroll
    for (int i = 0; i < 2; i++)
        bsts[i] = (uint32_t)(((kb + i * 16) * B_STRIDE_H + n8 * 8) * 2);

    float accg[4][4][4], accu[4][4][4];
#pragma unroll
    for (int mt = 0; mt < 4; mt++)
#pragma unroll
        for (int nt = 0; nt < 4; nt++)
#pragma unroll
            for (int c = 0; c < 4; c++) { accg[mt][nt][c] = 0.f; accu[mt][nt][c] = 0.f; }

    float4 vg[4], vu[4];

    auto ldgB = [&](int kt) {
        size_t k0 = (size_t)kt * BK * FF;
#pragma unroll
        for (int i = 0; i < 2; i++) {
            const float* g = bgp + k0 + (size_t)i * 16 * FF;
            const float* u = bup + k0 + (size_t)i * 16 * FF;
            vg[i * 2 + 0] = *(const float4*)(g);
            vg[i * 2 + 1] = *(const float4*)(g + 4);
            vu[i * 2 + 0] = *(const float4*)(u);
            vu[i * 2 + 1] = *(const float4*)(u + 4);
        }
    };
    auto ldA = [&](int kt, int b) {
        uint32_t sA = sb + b * GU_STAGE;
        int k0 = kt * BK;
        cp16(sA + asoA,      arow ? (const void*)(arow + k0 + q0)     : (const void*)g_xs, arow != nullptr);
        cp16(sA + asoA + 16, arow ? (const void*)(arow + k0 + q0 + 8) : (const void*)g_xs, arow != nullptr);
    };
    auto stsB = [&](int b) {
#pragma unroll
        for (int i = 0; i < 2; i++) {
            *(uint4*)((char*)smem + (b * GU_STAGE + A_BYTES) + bsts[i]) = pack8(vg[i * 2], vg[i * 2 + 1]);
            *(uint4*)((char*)smem + (b * GU_STAGE + A_BYTES + B_BYTES_H) + bsts[i]) = pack8(vu[i * 2], vu[i * 2 + 1]);
        }
    };

    ldgB(0);
    ldA(0, 0); CP_COMMIT();
    stsB(0);
    CP_WAIT0();
    __syncthreads();

    for (int kt = 0; kt < NKT; kt++) {
        int b = kt & 1;
        bool pre = (kt + 1 < NKT);
        if (pre) {
            ldgB(kt + 1);
            ldA(kt + 1, b ^ 1); CP_COMMIT();
        }
        uint32_t sA = sb + b * GU_STAGE;
        uint32_t sG = sA + A_BYTES;
        uint32_t sU = sG + B_BYTES_H;
        uint32_t abase = sA + a_lm;
        uint32_t gbase = sG + b_lm;
        uint32_t ubase = sU + b_lm;
#pragma unroll
        for (int kk = 0; kk < 2; kk++) {
            int kr = kk * 16;
            uint32_t af[4][4];
#pragma unroll
            for (int mt = 0; mt < 4; mt++)
                ldsm4(af[mt], abase + (uint32_t)((mt * 16 * A_STRIDE_H + kr) * 2));
            uint32_t bg[2][4], bu[2][4];
#pragma unroll
            for (int p = 0; p < 2; p++) {
                ldsm4t(bg[p], gbase + (uint32_t)((kr * B_STRIDE_H + p * 16) * 2));
                ldsm4t(bu[p], ubase + (uint32_t)((kr * B_STRIDE_H + p * 16) * 2));
            }
#pragma unroll
            for (int p = 0; p < 2; p++)
#pragma unroll
                for (int mt = 0; mt < 4; mt++) {
                    mma16(accg[mt][2 * p + 0], af[mt], bg[p][0], bg[p][1]);
                    mma16(accg[mt][2 * p + 1], af[mt], bg[p][2], bg[p][3]);
                    mma16(accu[mt][2 * p + 0], af[mt], bu[p][0], bu[p][1]);
                    mma16(accu[mt][2 * p + 1], af[mt], bu[p][2], bu[p][3]);
                }
        }
        if (pre) {
            stsB(b ^ 1);
            CP_WAIT0();
        }
        __syncthreads();
    }

    // ---- epilogue: h = fp16(silu(g) * u) ----
#pragma unroll
    for (int mt = 0; mt < 4; mt++) {
        int row0 = m0 + wm * 64 + mt * 16 + grp;
#pragma unroll
        for (int half = 0; half < 2; half++) {
            int r = row0 + half * 8;
            if (r < Mcnt) {
                __half* orow = Hout + (size_t)(base + r) * FF + n0 + wn * 32;
#pragma unroll
                for (int nt = 0; nt < 4; nt++) {
                    float gx = accg[mt][nt][half * 2 + 0];
                    float gy = accg[mt][nt][half * 2 + 1];
                    float hx = gx / (1.f + expf(-gx)) * accu[mt][nt][half * 2 + 0];
                    float hy = gy / (1.f + expf(-gy)) * accu[mt][nt][half * 2 + 1];
                    *(__half2*)(orow + nt * 8 + tg * 2) = __floats2half2_rn(hx, hy);
                }
            }
        }
    }
}

// ================= fused down GEMM: out = h·Wd[e] + hs·Wsd, single write =================
// BM=128, warp tile 64x32 (mt=4), 128 k-stages (two K=2048 passes), 2 CTAs/SM
__global__ void __launch_bounds__(256, 2) down_mma(const float* __restrict__ W_all,
                                                   const float* __restrict__ Wsd,
                                                   float* __restrict__ Out) {
    int e    = blockIdx.z;
    int Mcnt = g_counts[e];
    int base = g_offsets[e];
    int m0 = blockIdx.y * BM;
    if (m0 >= Mcnt) return;
    int n0 = blockIdx.x * BN;
    const float* W1 = W_all + (size_t)e * FF * DM;

    extern __shared__ char smem[];
    uint32_t sb = smem_u32(smem);
    int tid = threadIdx.x, wid = tid >> 5, lane = tid & 31;
    int wm = wid >> 2, wn = wid & 3;
    int grp = lane >> 2, tg = lane & 3;

    uint32_t a_lm = (uint32_t)((((lane & 15) + wm * 64) * A_STRIDE_H + (lane >> 4) * 8) * 2);
    uint32_t b_lm = (uint32_t)(((((lane & 7) + ((lane >> 3) & 1) * 8) * B_STRIDE_H)
                               + wn * 32 + (lane >> 4) * 8) * 2);

    // A: two sources — phase 0: g_h (permuted rows), phase 1: g_hs[token]
    const __half* arow1 = nullptr;
    const __half* arow2 = nullptr;
    uint32_t asoA;
    int q0 = (tid & 1) * 16;
    {
        int r = tid >> 1;
        int gr = m0 + r;
        if (gr < Mcnt) {
            arow1 = g_h + (size_t)(base + gr) * FF;
            arow2 = g_hs + (size_t)g_perm[base + gr] * FF;
        }
        asoA = (uint32_t)((r * A_STRIDE_H + q0) * 2);
    }
    int n8 = tid & 15, kb = tid >> 4;
    const float* wp1 = W1  + (size_t)kb * DM + n0 + n8 * 8;
    const float* wp2 = Wsd + (size_t)kb * DM + n0 + n8 * 8;
    uint32_t bsts[2];
#pragma unroll
    for (int i = 0; i < 2; i++)
        bsts[i] = (uint32_t)(((kb + i * 16) * B_STRIDE_H + n8 * 8) * 2);

    float acc[4][4][4];
#pragma unroll
    for (int mt = 0; mt < 4; mt++)
#pragma unroll
        for (int nt = 0; nt < 4; nt++)
#pragma unroll
            for (int c = 0; c < 4; c++) acc[mt][nt][c] = 0.f;

    float4 vw[4];

    auto ldgB = [&](int kt) {
        const float* wp = (kt >= NKT) ? wp2 : wp1;
        size_t k0 = (size_t)(kt & (NKT - 1)) * BK * DM;
#pragma unroll
        for (int i = 0; i < 2; i++) {
            const float* w = wp + k0 + (size_t)i * 16 * DM;
            vw[i * 2 + 0] = *(const float4*)(w);
            vw[i * 2 + 1] = *(const float4*)(w + 4);
        }
    };
    auto ldA = [&](int kt, int b) {
        const __half* ar = (kt >= NKT) ? arow2 : arow1;
        uint32_t sA = sb + b * DN_STAGE;
        int k0 = (kt & (NKT - 1)) * BK;
        cp16(sA + asoA,      ar ? (const void*)(ar + k0 + q0)     : (const void*)g_h, ar != nullptr);
        cp16(sA + asoA + 16, ar ? (const void*)(ar + k0 + q0 + 8) : (const void*)g_h, ar != nullptr);
    };
    auto stsB = [&](int b) {
#pragma unroll
        for (int i = 0; i < 2; i++)
            *(uint4*)((char*)smem + (b * DN_STAGE + A_BYTES) + bsts[i]) = pack8(vw[i * 2], vw[i * 2 + 1]);
    };

    ldgB(0);
    ldA(0, 0); CP_COMMIT();
    stsB(0);
    CP_WAIT0();
    __syncthreads();

    const int NKT2 = 2 * NKT;
    for (int kt = 0; kt < NKT2; kt++) {
        int b = kt & 1;
        bool pre = (kt + 1 < NKT2);
        if (pre) {
            ldgB(kt + 1);
            ldA(kt + 1, b ^ 1); CP_COMMIT();
        }
        uint32_t sA = sb + b * DN_STAGE;
        uint32_t sB = sA + A_BYTES;
        uint32_t abase = sA + a_lm;
        uint32_t bbase = sB + b_lm;
#pragma unroll
        for (int kk = 0; kk < 2; kk++) {
            int kr = kk * 16;
            uint32_t af[4][4];
#pragma unroll
            for (int mt = 0; mt < 4; mt++)
                ldsm4(af[mt], abase + (uint32_t)((mt * 16 * A_STRIDE_H + kr) * 2));
            uint32_t bf[2][4];
#pragma unroll
            for (int p = 0; p < 2; p++)
                ldsm4t(bf[p], bbase + (uint32_t)((kr * B_STRIDE_H + p * 16) * 2));
#pragma unroll
            for (int p = 0; p < 2; p++)
#pragma unroll
                for (int mt = 0; mt < 4; mt++) {
                    mma16(acc[mt][2 * p + 0], af[mt], bf[p][0], bf[p][1]);
                    mma16(acc[mt][2 * p + 1], af[mt], bf[p][2], bf[p][3]);
                }
        }
        if (pre) {
            stsB(b ^ 1);
            CP_WAIT0();
        }
        __syncthreads();
    }

    // ---- epilogue: single write, scatter to token rows ----
#pragma unroll
    for (int mt = 0; mt < 4; mt++) {
        int row0 = m0 + wm * 64 + mt * 16 + grp;
#pragma unroll
        for (int half = 0; half < 2; half++) {
            int r = row0 + half * 8;
            if (r < Mcnt) {
                int tok = g_perm[base + r];
                float* orow = Out + (size_t)tok * DM + n0 + wn * 32;
#pragma unroll
                for (int nt = 0; nt < 4; nt++) {
                    float vx = acc[mt][nt][half * 2 + 0];
                    float vy = acc[mt][nt][half * 2 + 1];
                    *(float2*)(orow + nt * 8 + tg * 2) = make_float2(vx, vy);
                }
            }
        }
    }
}

// ---------------- launch ----------------
extern "C" void kernel_launch(void* const* d_in, const int* in_sizes, int n_in,
                              void* d_out, int out_size) {
    const float* hidden   = (const float*)d_in[0];
    const float* router_w = (const float*)d_in[1];
    const float* gate_w   = (const float*)d_in[2];
    const float* up_w     = (const float*)d_in[3];
    const float* down_w   = (const float*)d_in[4];
    const float* sgate    = (const float*)d_in[5];
    const float* sup      = (const float*)d_in[6];
    const float* sdown    = (const float*)d_in[7];
    float* out = (float*)d_out;

    cudaFuncSetAttribute(gateup_mma, cudaFuncAttributeMaxDynamicSharedMemorySize, GU_SMEM);
    cudaFuncSetAttribute(down_mma,   cudaFuncAttributeMaxDynamicSharedMemorySize, DN_SMEM);

    init_kernel<<<1, 32>>>();
    router_kernel<<<T, 256>>>(hidden, router_w);
    scan_kernel<<<1, 32>>>();
    scatter_kernel<<<T / 256, 256>>>();

    dim3 gg(FF / BN, T / BM, NE + 1);   // 16 x 16 x 9; z 0..7 routed, 8 = shared
    gateup_mma<<<gg, 256, GU_SMEM>>>(gate_w, up_w, sgate, sup);

    dim3 dd(DM / BN, T / BM, NE);       // 16 x 16 x 8; fused routed+shared down, single write
    down_mma<<<dd, 256, DN_SMEM>>>(down_w, sdown, out);
}

// round 17
// speedup vs baseline: 1.0107x; 1.0020x over previous
#include <cuda_runtime.h>
#include <cuda_fp16.h>
#include <math.h>
#include <stdint.h>

#define T 2048      // tokens
#define DM 2048     // model dim
#define FF 2048     // ffn dim
#define NE 8        // experts
#define BM 128
#define BN 128
#define BK 32
#define NKT (DM/BK)   // 64 k-stages per K=2048 GEMM

// smem layout (all fp16)
#define A_STRIDE_H 40                      // halfs per A row (32+8 pad): ldsm conflict-free
#define B_STRIDE_H 136                     // halfs per B row (128+8 pad): ldsm.trans conflict-free
#define A_BYTES (BM * A_STRIDE_H * 2)      // 10240
#define B_BYTES_H (BK * B_STRIDE_H * 2)    // 8704
#define GU_STAGE (A_BYTES + 2 * B_BYTES_H) // 27648
#define GU_SMEM  (2 * GU_STAGE)            // 55296
#define DN_STAGE (A_BYTES + B_BYTES_H)     // 18944
#define DN_SMEM  (2 * DN_STAGE)            // 37888

// ---------------- scratch (device globals) ----------------
__device__ __align__(16) __half g_xs[(size_t)T * DM];   // fp16(x * score)
__device__ __align__(16) __half g_xr[(size_t)T * DM];   // fp16(x)
__device__ __align__(16) __half g_h [(size_t)T * FF];   // fp16(routed swiglu), permuted rows
__device__ __align__(16) __half g_hs[(size_t)T * FF];   // fp16(shared swiglu), token rows
__device__ int g_eidx[T];
__device__ int g_counts[NE];
__device__ int g_offsets[NE];
__device__ int g_cursor[NE];
__device__ int g_perm[T];

// ---------------- PTX helpers ----------------
__device__ __forceinline__ void cp16(uint32_t dst, const void* src, bool pred) {
    int bytes = pred ? 16 : 0;
    asm volatile("cp.async.cg.shared.global [%0], [%1], 16, %2;"
                 :: "r"(dst), "l"(src), "r"(bytes) : "memory");
}
#define CP_COMMIT() asm volatile("cp.async.commit_group;" ::: "memory")
#define CP_WAIT0()  asm volatile("cp.async.wait_group 0;" ::: "memory")

__device__ __forceinline__ uint32_t smem_u32(const void* p) {
    uint32_t a;
    asm("{ .reg .u64 t; cvta.to.shared.u64 t, %1; cvt.u32.u64 %0, t; }" : "=r"(a) : "l"(p));
    return a;
}
__device__ __forceinline__ uint32_t h2(float hi, float lo) {
    uint32_t d;
    asm("cvt.rn.f16x2.f32 %0, %1, %2;" : "=r"(d) : "f"(hi), "f"(lo));
    return d;
}
__device__ __forceinline__ void mma16(float* c, const uint32_t* a, uint32_t b0, uint32_t b1) {
    asm volatile("mma.sync.aligned.m16n8k16.row.col.f32.f16.f16.f32 "
                 "{%0,%1,%2,%3}, {%4,%5,%6,%7}, {%8,%9}, {%0,%1,%2,%3};"
                 : "+f"(c[0]), "+f"(c[1]), "+f"(c[2]), "+f"(c[3])
                 : "r"(a[0]), "r"(a[1]), "r"(a[2]), "r"(a[3]), "r"(b0), "r"(b1));
}
__device__ __forceinline__ void ldsm4(uint32_t* r, uint32_t addr) {
    asm volatile("ldmatrix.sync.aligned.m8n8.x4.shared.b16 {%0,%1,%2,%3}, [%4];"
                 : "=r"(r[0]), "=r"(r[1]), "=r"(r[2]), "=r"(r[3]) : "r"(addr));
}
__device__ __forceinline__ void ldsm4t(uint32_t* r, uint32_t addr) {
    asm volatile("ldmatrix.sync.aligned.m8n8.x4.trans.shared.b16 {%0,%1,%2,%3}, [%4];"
                 : "=r"(r[0]), "=r"(r[1]), "=r"(r[2]), "=r"(r[3]) : "r"(addr));
}
__device__ __forceinline__ uint4 pack8(float4 v0, float4 v1) {
    uint4 o;
    o.x = h2(v0.y, v0.x); o.y = h2(v0.w, v0.z);
    o.z = h2(v1.y, v1.x); o.w = h2(v1.w, v1.z);
    return o;
}

// ---------------- router / routing bookkeeping ----------------
__global__ void init_kernel() { if (threadIdx.x < NE) g_counts[threadIdx.x] = 0; }

__global__ void __launch_bounds__(256) router_kernel(const float* __restrict__ x,
                                                     const float* __restrict__ rw) {
    int t = blockIdx.x;
    const float* xr = x + (size_t)t * DM;
    float acc[NE];
#pragma unroll
    for (int e = 0; e < NE; e++) acc[e] = 0.f;
    for (int d = threadIdx.x; d < DM; d += 256) {
        float xv = xr[d];
        const float* r = rw + (size_t)d * NE;
#pragma unroll
        for (int e = 0; e < NE; e++) acc[e] = fmaf(xv, r[e], acc[e]);
    }
    __shared__ float sacc[8][NE];
    __shared__ float s_score;
    int lane = threadIdx.x & 31, warp = threadIdx.x >> 5;
#pragma unroll
    for (int e = 0; e < NE; e++) {
        float v = acc[e];
#pragma unroll
        for (int o = 16; o > 0; o >>= 1) v += __shfl_down_sync(0xffffffffu, v, o);
        if (lane == 0) sacc[warp][e] = v;
    }
    __syncthreads();
    if (threadIdx.x == 0) {
        float best = -INFINITY; int bi = 0;
#pragma unroll
        for (int e = 0; e < NE; e++) {
            float v = 0.f;
#pragma unroll
            for (int w = 0; w < 8; w++) v += sacc[w][e];
            if (v > best) { best = v; bi = e; }
        }
        s_score = 1.f / (1.f + expf(-best));
        g_eidx[t] = bi;
        atomicAdd(&g_counts[bi], 1);
    }
    __syncthreads();
    float sc = s_score;
    for (int d = threadIdx.x; d < DM; d += 256) {
        float xv = xr[d];
        g_xs[(size_t)t * DM + d] = __float2half_rn(xv * sc);
        g_xr[(size_t)t * DM + d] = __float2half_rn(xv);
    }
}

__global__ void scan_kernel() {
    if (threadIdx.x == 0) {
        int off = 0;
        for (int e = 0; e < NE; e++) { g_offsets[e] = off; g_cursor[e] = off; off += g_counts[e]; }
    }
}
__global__ void scatter_kernel() {
    int t = blockIdx.x * blockDim.x + threadIdx.x;
    if (t < T) { int e = g_eidx[t]; int pos = atomicAdd(&g_cursor[e], 1); g_perm[pos] = t; }
}

// ================= gate/up GEMM + fused SwiGLU (merged routed z<8 / shared z==8) =================
// 256 threads, 8 warps 2x4, warp tile 64x32 (mt=4, nt=4), BM=128
__global__ void __launch_bounds__(256) gateup_mma(const float* __restrict__ Wg_all,
                                                  const float* __restrict__ Wu_all,
                                                  const float* __restrict__ Wsg,
                                                  const float* __restrict__ Wsu) {
    int e = blockIdx.z;
    bool sh = (e == NE);
    int Mcnt = sh ? T : g_counts[e];
    int base = sh ? 0 : g_offsets[e];
    int m0 = blockIdx.y * BM;
    if (m0 >= Mcnt) return;
    int n0 = blockIdx.x * BN;
    const __half* A = sh ? g_xr : g_xs;
    __half* Hout = sh ? g_hs : g_h;
    const float* Wg = sh ? Wsg : Wg_all + (size_t)e * DM * FF;
    const float* Wu = sh ? Wsu : Wu_all + (size_t)e * DM * FF;

    extern __shared__ char smem[];
    uint32_t sb = smem_u32(smem);
    int tid = threadIdx.x, wid = tid >> 5, lane = tid & 31;
    int wm = wid >> 2, wn = wid & 3;
    int grp = lane >> 2, tg = lane & 3;

    uint32_t a_lm = (uint32_t)((((lane & 15) + wm * 64) * A_STRIDE_H + (lane >> 4) * 8) * 2);
    uint32_t b_lm = (uint32_t)(((((lane & 7) + ((lane >> 3) & 1) * 8) * B_STRIDE_H)
                               + wn * 32 + (lane >> 4) * 8) * 2);

    // ---- A copy: row tid/2, 16-half chunk (tid&1) ----
    const __half* arow = nullptr;
    uint32_t asoA;
    int q0 = (tid & 1) * 16;
    {
        int r = tid >> 1;
        int gr = m0 + r;
        if (gr < Mcnt) {
            int tok = sh ? gr : g_perm[base + gr];
            arow = A + (size_t)tok * DM;
        }
        asoA = (uint32_t)((r * A_STRIDE_H + q0) * 2);
    }
    // ---- B load/convert: n8 = tid&15 (8-float chunk), kb = tid>>4 -> rows kb, kb+16 ----
    int n8 = tid & 15, kb = tid >> 4;
    const float* bgp = Wg + (size_t)kb * FF + n0 + n8 * 8;
    const float* bup = Wu + (size_t)kb * FF + n0 + n8 * 8;
    uint32_t bsts[2];
#pragma unroll
    for (int i = 0; i < 2; i++)
        bsts[i] = (uint32_t)(((kb + i * 16) * B_STRIDE_H + n8 * 8) * 2);

    float accg[4][4][4], accu[4][4][4];
#pragma unroll
    for (int mt = 0; mt < 4; mt++)
#pragma unroll
        for (int nt = 0; nt < 4; nt++)
#pragma unroll
            for (int c = 0; c < 4; c++) { accg[mt][nt][c] = 0.f; accu[mt][nt][c] = 0.f; }

    float4 vg[4], vu[4];

    auto ldgB = [&](int kt) {
        size_t k0 = (size_t)kt * BK * FF;
#pragma unroll
        for (int i = 0; i < 2; i++) {
            const float* g = bgp + k0 + (size_t)i * 16 * FF;
            const float* u = bup + k0 + (size_t)i * 16 * FF;
            vg[i * 2 + 0] = *(const float4*)(g);
            vg[i * 2 + 1] = *(const float4*)(g + 4);
            vu[i * 2 + 0] = *(const float4*)(u);
            vu[i * 2 + 1] = *(const float4*)(u + 4);
        }
    };
    auto ldA = [&](int kt, int b) {
        uint32_t sA = sb + b * GU_STAGE;
        int k0 = kt * BK;
        cp16(sA + asoA,      arow ? (const void*)(arow + k0 + q0)     : (const void*)g_xs, arow != nullptr);
        cp16(sA + asoA + 16, arow ? (const void*)(arow + k0 + q0 + 8) : (const void*)g_xs, arow != nullptr);
    };
    auto stsB = [&](int b) {
#pragma unroll
        for (int i = 0; i < 2; i++) {
            *(uint4*)((char*)smem + (b * GU_STAGE + A_BYTES) + bsts[i]) = pack8(vg[i * 2], vg[i * 2 + 1]);
            *(uint4*)((char*)smem + (b * GU_STAGE + A_BYTES + B_BYTES_H) + bsts[i]) = pack8(vu[i * 2], vu[i * 2 + 1]);
        }
    };

    ldgB(0);
    ldA(0, 0); CP_COMMIT();
    stsB(0);
    CP_WAIT0();
    __syncthreads();

    for (int kt = 0; kt < NKT; kt++) {
        int b = kt & 1;
        bool pre = (kt + 1 < NKT);
        if (pre) {
            ldgB(kt + 1);
            ldA(kt + 1, b ^ 1); CP_COMMIT();
        }
        uint32_t sA = sb + b * GU_STAGE;
        uint32_t sG = sA + A_BYTES;
        uint32_t sU = sG + B_BYTES_H;
        uint32_t abase = sA + a_lm;
        uint32_t gbase = sG + b_lm;
        uint32_t ubase = sU + b_lm;
#pragma unroll
        for (int kk = 0; kk < 2; kk++) {
            int kr = kk * 16;
            uint32_t af[4][4];
#pragma unroll
            for (int mt = 0; mt < 4; mt++)
                ldsm4(af[mt], abase + (uint32_t)((mt * 16 * A_STRIDE_H + kr) * 2));
            uint32_t bg[2][4], bu[2][4];
#pragma unroll
            for (int p = 0; p < 2; p++) {
                ldsm4t(bg[p], gbase + (uint32_t)((kr * B_STRIDE_H + p * 16) * 2));
                ldsm4t(bu[p], ubase + (uint32_t)((kr * B_STRIDE_H + p * 16) * 2));
            }
#pragma unroll
            for (int p = 0; p < 2; p++)
#pragma unroll
                for (int mt = 0; mt < 4; mt++) {
                    mma16(accg[mt][2 * p + 0], af[mt], bg[p][0], bg[p][1]);
                    mma16(accg[mt][2 * p + 1], af[mt], bg[p][2], bg[p][3]);
                    mma16(accu[mt][2 * p + 0], af[mt], bu[p][0], bu[p][1]);
                    mma16(accu[mt][2 * p + 1], af[mt], bu[p][2], bu[p][3]);
                }
        }
        if (pre) {
            stsB(b ^ 1);
            CP_WAIT0();
        }
        __syncthreads();
    }

    // ---- epilogue: h = fp16(silu(g) * u) ----
#pragma unroll
    for (int mt = 0; mt < 4; mt++) {
        int row0 = m0 + wm * 64 + mt * 16 + grp;
#pragma unroll
        for (int half = 0; half < 2; half++) {
            int r = row0 + half * 8;
            if (r < Mcnt) {
                __half* orow = Hout + (size_t)(base + r) * FF + n0 + wn * 32;
#pragma unroll
                for (int nt = 0; nt < 4; nt++) {
                    float gx = accg[mt][nt][half * 2 + 0];
                    float gy = accg[mt][nt][half * 2 + 1];
                    float hx = gx / (1.f + expf(-gx)) * accu[mt][nt][half * 2 + 0];
                    float hy = gy / (1.f + expf(-gy)) * accu[mt][nt][half * 2 + 1];
                    *(__half2*)(orow + nt * 8 + tg * 2) = __floats2half2_rn(hx, hy);
                }
            }
        }
    }
}

// ================= fused down GEMM: out = h·Wd[e] + hs·Wsd, single write =================
// BM=128, warp tile 64x32 (mt=4), 128 k-stages (two K=2048 passes), natural regs (no occ cap)
__global__ void __launch_bounds__(256) down_mma(const float* __restrict__ W_all,
                                                const float* __restrict__ Wsd,
                                                float* __restrict__ Out) {
    int e    = blockIdx.z;
    int Mcnt = g_counts[e];
    int base = g_offsets[e];
    int m0 = blockIdx.y * BM;
    if (m0 >= Mcnt) return;
    int n0 = blockIdx.x * BN;
    const float* W1 = W_all + (size_t)e * FF * DM;

    extern __shared__ char smem[];
    uint32_t sb = smem_u32(smem);
    int tid = threadIdx.x, wid = tid >> 5, lane = tid & 31;
    int wm = wid >> 2, wn = wid & 3;
    int grp = lane >> 2, tg = lane & 3;

    uint32_t a_lm = (uint32_t)((((lane & 15) + wm * 64) * A_STRIDE_H + (lane >> 4) * 8) * 2);
    uint32_t b_lm = (uint32_t)(((((lane & 7) + ((lane >> 3) & 1) * 8) * B_STRIDE_H)
                               + wn * 32 + (lane >> 4) * 8) * 2);

    // A: two sources — phase 0: g_h (permuted rows), phase 1: g_hs[token]
    const __half* arow1 = nullptr;
    const __half* arow2 = nullptr;
    uint32_t asoA;
    int q0 = (tid & 1) * 16;
    {
        int r = tid >> 1;
        int gr = m0 + r;
        if (gr < Mcnt) {
            arow1 = g_h + (size_t)(base + gr) * FF;
            arow2 = g_hs + (size_t)g_perm[base + gr] * FF;
        }
        asoA = (uint32_t)((r * A_STRIDE_H + q0) * 2);
    }
    int n8 = tid & 15, kb = tid >> 4;
    const float* wp1 = W1  + (size_t)kb * DM + n0 + n8 * 8;
    const float* wp2 = Wsd + (size_t)kb * DM + n0 + n8 * 8;
    uint32_t bsts[2];
#pragma unroll
    for (int i = 0; i < 2; i++)
        bsts[i] = (uint32_t)(((kb + i * 16) * B_STRIDE_H + n8 * 8) * 2);

    float acc[4][4][4];
#pragma unroll
    for (int mt = 0; mt < 4; mt++)
#pragma unroll
        for (int nt = 0; nt < 4; nt++)
#pragma unroll
            for (int c = 0; c < 4; c++) acc[mt][nt][c] = 0.f;

    float4 vw[4];

    auto ldgB = [&](int kt) {
        const float* wp = (kt >= NKT) ? wp2 : wp1;
        size_t k0 = (size_t)(kt & (NKT - 1)) * BK * DM;
#pragma unroll
        for (int i = 0; i < 2; i++) {
            const float* w = wp + k0 + (size_t)i * 16 * DM;
            vw[i * 2 + 0] = *(const float4*)(w);
            vw[i * 2 + 1] = *(const float4*)(w + 4);
        }
    };
    auto ldA = [&](int kt, int b) {
        const __half* ar = (kt >= NKT) ? arow2 : arow1;
        uint32_t sA = sb + b * DN_STAGE;
        int k0 = (kt & (NKT - 1)) * BK;
        cp16(sA + asoA,      ar ? (const void*)(ar + k0 + q0)     : (const void*)g_h, ar != nullptr);
        cp16(sA + asoA + 16, ar ? (const void*)(ar + k0 + q0 + 8) : (const void*)g_h, ar != nullptr);
    };
    auto stsB = [&](int b) {
#pragma unroll
        for (int i = 0; i < 2; i++)
            *(uint4*)((char*)smem + (b * DN_STAGE + A_BYTES) + bsts[i]) = pack8(vw[i * 2], vw[i * 2 + 1]);
    };

    ldgB(0);
    ldA(0, 0); CP_COMMIT();
    stsB(0);
    CP_WAIT0();
    __syncthreads();

    const int NKT2 = 2 * NKT;
    for (int kt = 0; kt < NKT2; kt++) {
        int b = kt & 1;
        bool pre = (kt + 1 < NKT2);
        if (pre) {
            ldgB(kt + 1);
            ldA(kt + 1, b ^ 1); CP_COMMIT();
        }
        uint32_t sA = sb + b * DN_STAGE;
        uint32_t sB = sA + A_BYTES;
        uint32_t abase = sA + a_lm;
        uint32_t bbase = sB + b_lm;
#pragma unroll
        for (int kk = 0; kk < 2; kk++) {
            int kr = kk * 16;
            uint32_t af[4][4];
#pragma unroll
            for (int mt = 0; mt < 4; mt++)
                ldsm4(af[mt], abase + (uint32_t)((mt * 16 * A_STRIDE_H + kr) * 2));
            uint32_t bf[2][4];
#pragma unroll
            for (int p = 0; p < 2; p++)
                ldsm4t(bf[p], bbase + (uint32_t)((kr * B_STRIDE_H + p * 16) * 2));
#pragma unroll
            for (int p = 0; p < 2; p++)
#pragma unroll
                for (int mt = 0; mt < 4; mt++) {
                    mma16(acc[mt][2 * p + 0], af[mt], bf[p][0], bf[p][1]);
                    mma16(acc[mt][2 * p + 1], af[mt], bf[p][2], bf[p][3]);
                }
        }
        if (pre) {
            stsB(b ^ 1);
            CP_WAIT0();
        }
        __syncthreads();
    }

    // ---- epilogue: single write, scatter to token rows ----
#pragma unroll
    for (int mt = 0; mt < 4; mt++) {
        int row0 = m0 + wm * 64 + mt * 16 + grp;
#pragma unroll
        for (int half = 0; half < 2; half++) {
            int r = row0 + half * 8;
            if (r < Mcnt) {
                int tok = g_perm[base + r];
                float* orow = Out + (size_t)tok * DM + n0 + wn * 32;
#pragma unroll
                for (int nt = 0; nt < 4; nt++) {
                    float vx = acc[mt][nt][half * 2 + 0];
                    float vy = acc[mt][nt][half * 2 + 1];
                    *(float2*)(orow + nt * 8 + tg * 2) = make_float2(vx, vy);
                }
            }
        }
    }
}

// ---------------- launch ----------------
extern "C" void kernel_launch(void* const* d_in, const int* in_sizes, int n_in,
                              void* d_out, int out_size) {
    const float* hidden   = (const float*)d_in[0];
    const float* router_w = (const float*)d_in[1];
    const float* gate_w   = (const float*)d_in[2];
    const float* up_w     = (const float*)d_in[3];
    const float* down_w   = (const float*)d_in[4];
    const float* sgate    = (const float*)d_in[5];
    const float* sup      = (const float*)d_in[6];
    const float* sdown    = (const float*)d_in[7];
    float* out = (float*)d_out;

    cudaFuncSetAttribute(gateup_mma, cudaFuncAttributeMaxDynamicSharedMemorySize, GU_SMEM);
    cudaFuncSetAttribute(down_mma,   cudaFuncAttributeMaxDynamicSharedMemorySize, DN_SMEM);

    init_kernel<<<1, 32>>>();
    router_kernel<<<T, 256>>>(hidden, router_w);
    scan_kernel<<<1, 32>>>();
    scatter_kernel<<<T / 256, 256>>>();

    dim3 gg(FF / BN, T / BM, NE + 1);   // 16 x 16 x 9; z 0..7 routed, 8 = shared
    gateup_mma<<<gg, 256, GU_SMEM>>>(gate_w, up_w, sgate, sup);

    dim3 dd(DM / BN, T / BM, NE);       // 16 x 16 x 8; fused routed+shared down, single write
    down_mma<<<dd, 256, DN_SMEM>>>(down_w, sdown, out);
}